// round 13
// baseline (speedup 1.0000x reference)
#include <cuda_runtime.h>
#include <cstdint>
#include <cstddef>

// Problem constants
#define BATCH 8
#define TSEQ  1024
#define DDIM  384
#define DLANG 768
#define HID   512

#define NB   128      // one wave; 8 independent groups of 16 blocks
#define NTHR 512
#define GRPB 16       // blocks per batch group

// Scratch + barrier state (allocation-free rule: __device__ globals)
__device__ float g_bufA[BATCH * HID];
__device__ float g_bufB[BATCH * HID];
__device__ float g_f[BATCH * DDIM];
__device__ unsigned g_gbar[BATCH][4];   // per-group monotonic tickets; never reset

// Dynamic smem layout:
//   float4 tile[6144] : 98304 B (state tile: 64 rows x 96 float4)
//   float  sin[768]   :  3072 B (stage input vector)
//   float  spart[512] :  2048 B (16 kslices x 32 cols)
//   float4 fsh[96]    :  1536 B (f row)
//   uint64 mbar       :    16 B
#define TILE_F4 6144
#define SMEM_BYTES (TILE_F4 * 16 + DLANG * 4 + 512 * 4 + 96 * 16 + 16)

extern __shared__ float4 smem_dyn[];

__device__ __forceinline__ uint32_t smem_u32(const void* p) {
    return (uint32_t)__cvta_generic_to_shared(p);
}

// ---------------------------------------------------------------------------
// Per-group (16-block) ticket barrier: monotonic, no reset across replays.
// ALL 16 blocks of a group arrive at every phase (inactive blocks arrive
// too), so each counter is a clean multiple of 16 at phase entry of every
// launch/replay. Longer nanosleep = fewer L2 probe loads while spinning.
// ---------------------------------------------------------------------------
__device__ __forceinline__ void group_barrier(int grp, int phase) {
    __syncthreads();
    if (threadIdx.x == 0) {
        __threadfence();
        const unsigned old = atomicAdd(&g_gbar[grp][phase], 1u);
        const unsigned target = old - (old & (GRPB - 1)) + GRPB;
        volatile unsigned* p = &g_gbar[grp][phase];
        while ((int)(*p - target) < 0) { __nanosleep(64); }
        __threadfence();
    }
    __syncthreads();
}

// ---------------------------------------------------------------------------
// One GEMV stage, batch-local: group grp (16 blocks) computes
//   out[grp, :] = in[grp, :] @ W + bias          (W row-major [K, N])
// Block jt handles cols [jt*32, jt*32+32); jt >= N/32 -> inactive (but still
// participates in barriers). Thread (ks, jj): ks = k-slice 0..15, jj = col.
// Weight loads: 32 consecutive j per warp -> fully coalesced 128B lines.
// ---------------------------------------------------------------------------
template <int K, int N>
__device__ __forceinline__ void chain_stage(int grp, int jt,
                                            const float* __restrict__ in,
                                            const float* __restrict__ W,
                                            const float* __restrict__ bias,
                                            float* __restrict__ out,
                                            float* sin, float* spart) {
    constexpr int JT = N / 32;
    constexpr int KW = K / 16;

    for (int i = threadIdx.x; i < K; i += NTHR)
        sin[i] = in[(size_t)grp * K + i];
    __syncthreads();

    if (jt < JT) {
        const int ks = threadIdx.x >> 5;          // 0..15
        const int jj = threadIdx.x & 31;
        const int j  = jt * 32 + jj;
        const float* Wp = W + (size_t)(ks * KW) * N + j;
        const float* sp = sin + ks * KW;
        float acc = 0.0f;
#pragma unroll
        for (int i = 0; i < KW; ++i)
            acc += sp[i] * Wp[(size_t)i * N];
        spart[ks * 32 + jj] = acc;
    }
    __syncthreads();

    if (jt < JT && threadIdx.x < 32) {
        const int j = jt * 32 + threadIdx.x;
        float s = bias[j];
#pragma unroll
        for (int k = 0; k < 16; ++k) s += spart[k * 32 + threadIdx.x];
        out[(size_t)grp * N + j] = s;
    }
    // sin/spart reuse by the next stage is protected by group_barrier's syncs.
}

// ---------------------------------------------------------------------------
// Fused kernel: 8 independent batch groups, each 16 blocks.
//
// Math note: language is broadcast along T, so k/v are identical for all key
// positions; softmax over a constant row is exactly uniform 1/T and ctx == v.
// The Q path and the T x T attention cancel analytically:
//   f[b] = (((language[b] Wv + bv) Wv2 + bv2) Wo + bo) Wout + bout
//   out[b,t,:] = state[b,t,:] + f[b,:]
//
// The chain is batch-diagonal, so groups never synchronize with each other:
// only 16-block barriers (cheap arrive, tiny straggler exposure). The 96KB
// state tile streams on the TMA pipe during the whole chain.
// ---------------------------------------------------------------------------
__global__ void __launch_bounds__(NTHR, 1)
fused_cma_kernel(const float* __restrict__ state,
                 const float* __restrict__ language,
                 const float* __restrict__ Wv,  const float* __restrict__ bv,
                 const float* __restrict__ Wv2, const float* __restrict__ bv2,
                 const float* __restrict__ Wo,  const float* __restrict__ bo,
                 const float* __restrict__ Wout,const float* __restrict__ bout,
                 float* __restrict__ out) {
    float4*   tile  = smem_dyn;                              // 6144 float4
    float*    sin   = (float*)(smem_dyn + TILE_F4);          // 768 floats
    float*    spart = sin + DLANG;                           // 512 floats
    float4*   fsh   = (float4*)(spart + 512);                // 96 float4
    uint64_t* mbar  = (uint64_t*)(fsh + 96);

    const int grp = blockIdx.x >> 4;                         // batch group
    const int jt  = blockIdx.x & 15;                         // tile in group

    // ---- Issue state-tile bulk copy first (TMA pipe; overlaps the chain) ----
    const int t0 = jt * 64;                                  // row start
    const size_t base = ((size_t)grp * TSEQ + t0) * DDIM;

    const uint32_t mbar_s = smem_u32(mbar);
    const uint32_t tile_s = smem_u32(tile);
    if (threadIdx.x == 0) {
        asm volatile("mbarrier.init.shared.b64 [%0], 1;" :: "r"(mbar_s) : "memory");
        asm volatile("fence.proxy.async.shared::cta;" ::: "memory");
        asm volatile("mbarrier.arrive.expect_tx.shared.b64 _, [%0], %1;"
                     :: "r"(mbar_s), "r"((unsigned)(TILE_F4 * 16)) : "memory");
        asm volatile(
            "cp.async.bulk.shared::cta.global.mbarrier::complete_tx::bytes "
            "[%0], [%1], %2, [%3];"
            :: "r"(tile_s), "l"(state + base), "r"((unsigned)(TILE_F4 * 16)),
               "r"(mbar_s) : "memory");
    }

    // ---- GEMV chain, batch-local (only 16-block barriers) ----
    chain_stage<DLANG, HID>(grp, jt, language, Wv,   bv,   g_bufA, sin, spart);
    group_barrier(grp, 0);
    chain_stage<HID,   HID>(grp, jt, g_bufA,   Wv2,  bv2,  g_bufB, sin, spart);
    group_barrier(grp, 1);
    chain_stage<HID,   HID>(grp, jt, g_bufB,   Wo,   bo,   g_bufA, sin, spart);
    group_barrier(grp, 2);
    chain_stage<HID,  DDIM>(grp, jt, g_bufA,   Wout, bout, g_f,    sin, spart);
    group_barrier(grp, 3);                                   // f[grp] ready

    // ---- f row into smem (dense, same group) ----
    if (threadIdx.x < DDIM / 4) {
        fsh[threadIdx.x] =
            ((const float4*)(g_f + (size_t)grp * DDIM))[threadIdx.x];
    }
    __syncthreads();

    // Register-resident f: p = tid + it*512; 512 mod 96 = 32 -> period 3.
    const int dq0 = threadIdx.x % (DDIM / 4);
    const float4 f0 = fsh[dq0];
    const float4 f1 = fsh[(dq0 + 32) % (DDIM / 4)];
    const float4 f2 = fsh[(dq0 + 64) % (DDIM / 4)];

    // ---- Wait for the state tile (mbarrier parity 0, acquire) ----
    {
        uint32_t done;
        asm volatile(
            "{\n\t.reg .pred p;\n\t"
            "mbarrier.try_wait.parity.acquire.cta.shared::cta.b64 p, [%1], 0;\n\t"
            "selp.b32 %0, 1, 0, p;\n\t}"
            : "=r"(done) : "r"(mbar_s) : "memory");
        if (!done) {
            asm volatile(
                "{\n\t.reg .pred P1;\n\t"
                "WL_%=:\n\t"
                "mbarrier.try_wait.parity.acquire.cta.shared::cta.b64 P1, [%0], 0, 0x989680;\n\t"
                "@P1 bra.uni WD_%=;\n\t"
                "bra.uni WL_%=;\n\t"
                "WD_%=:\n\t}"
                :: "r"(mbar_s) : "memory");
        }
    }

    // ---- Residual add + store: 6144 float4 per block, 12 per thread ----
    float4* op = (float4*)(out + base);
#pragma unroll
    for (int it = 0; it < 12; ++it) {
        const int p = threadIdx.x + it * NTHR;
        float4 s = tile[p];
        const float4 fv = (it % 3 == 0) ? f0 : ((it % 3 == 1) ? f1 : f2);
        s.x += fv.x; s.y += fv.y; s.z += fv.z; s.w += fv.w;
        op[p] = s;
    }
}

// ---------------------------------------------------------------------------
// Inputs (metadata order):
//  0 state [B,T,D]   1 language [B,DL]
//  2 Wq 3 bq 4 Wk 5 bk 6 Wv 7 bv
//  8 Wq2 9 bq2 10 Wk2 11 bk2 12 Wv2 13 bv2
// 14 Wo 15 bo 16 Wout 17 bout
// Output: float32 [B,T,D]
// ---------------------------------------------------------------------------
extern "C" void kernel_launch(void* const* d_in, const int* in_sizes, int n_in,
                              void* d_out, int out_size) {
    (void)in_sizes; (void)n_in; (void)out_size;

    const float* state    = (const float*)d_in[0];
    const float* language = (const float*)d_in[1];
    const float* Wv   = (const float*)d_in[6];
    const float* bv   = (const float*)d_in[7];
    const float* Wv2  = (const float*)d_in[12];
    const float* bv2  = (const float*)d_in[13];
    const float* Wo   = (const float*)d_in[14];
    const float* bo   = (const float*)d_in[15];
    const float* Wout = (const float*)d_in[16];
    const float* bout = (const float*)d_in[17];
    float* out = (float*)d_out;

    cudaFuncSetAttribute(fused_cma_kernel,
                         cudaFuncAttributeMaxDynamicSharedMemorySize,
                         SMEM_BYTES);

    // Single graph node: ticket barriers need no reset across replays.
    fused_cma_kernel<<<NB, NTHR, SMEM_BYTES>>>(state, language,
                                               Wv, bv, Wv2, bv2, Wo, bo,
                                               Wout, bout, out);
}